// round 2
// baseline (speedup 1.0000x reference)
#include <cuda_runtime.h>
#include <cuda_bf16.h>
#include <math.h>

#define NI 32
#define NH 1024
#define NO 64
#define MB 8
#define THREADS 512

// Scratch (no device allocation allowed): transposed weights.
__device__ float g_W1T[NI * NH];     // [i][h]
__device__ float g_W2T[NH * NH];     // [h][g]  (W2T[h*NH+g] = W2[g*NH+h])
__device__ float g_W3T[NH * NO];     // [g][o]

// ---------------- prep kernels ----------------

__global__ void prep_small(const float* __restrict__ W1,
                           const float* __restrict__ W3) {
    int t = blockIdx.x * blockDim.x + threadIdx.x;
    if (t < NI * NH) {
        int i = t >> 10;       // /NH
        int h = t & (NH - 1);
        g_W1T[t] = W1[h * NI + i];
    }
    if (t < NH * NO) {
        int g = t >> 6;        // /NO
        int o = t & (NO - 1);
        g_W3T[t] = W3[o * NH + g];
    }
}

__global__ void prep_w2(const float* __restrict__ W2) {
    __shared__ float tile[32][33];
    int bx = blockIdx.x, by = blockIdx.y;
    int tx = threadIdx.x, ty = threadIdx.y;   // 32 x 8
    #pragma unroll
    for (int yy = 0; yy < 32; yy += 8)
        tile[ty + yy][tx] = W2[(by * 32 + ty + yy) * NH + bx * 32 + tx];
    __syncthreads();
    #pragma unroll
    for (int yy = 0; yy < 32; yy += 8)
        g_W2T[(bx * 32 + ty + yy) * NH + by * 32 + tx] = tile[tx][ty + yy];
}

// ---------------- main kernel ----------------
//
// Per CTA: MB batch rows. Running pre-activations z1[MB][NH], z2[MB][NH],
// z3[MB][64] in smem. 32 sequential steps; at step i only ~33 hidden units
// (degree == i) become final and are pushed forward as rank-33 updates.
// Degree of hidden unit h is h % 31. Valid update targets at step i are
// units with (h % 31) >= i: enumerated compactly via j -> (q = j/w,
// r = i + j%w, h = 31q + r) with w = 31 - i.

__global__ void __launch_bounds__(THREADS)
made_kernel(const float* __restrict__ inp,
            const float* __restrict__ b1,
            const float* __restrict__ b2,
            const float* __restrict__ b3,
            float* __restrict__ out, int B) {
    extern __shared__ float smem[];
    float* z1s = smem;                    // MB*NH
    float* z2s = z1s + MB * NH;           // MB*NH
    float* z3s = z2s + MB * NH;           // MB*NO
    float* xs  = z3s + MB * NO;           // MB*NI
    float* h1g = xs  + MB * NI;           // 34*MB  (layout [k][mb], 16B aligned)
    float* h2g = h1g + 34 * MB;           // 34*MB
    float* Js  = h2g + 34 * MB;           // MB

    const int tid = threadIdx.x;
    const int b0  = blockIdx.x * MB;

    // init state with biases
    for (int idx = tid; idx < MB * NH; idx += THREADS) {
        int h = idx & (NH - 1);
        z1s[idx] = b1[h];
        z2s[idx] = b2[h];
    }
    for (int idx = tid; idx < MB * NO; idx += THREADS)
        z3s[idx] = b3[idx & (NO - 1)];
    if (tid < MB) Js[tid] = 0.f;
    __syncthreads();

    for (int i = 0; i < NI; ++i) {
        // ---- Phase A: read p[:,i], p[:,32+i]; produce x_i ----
        if (tid < MB) {
            float m = z3s[tid * NO + i];
            float a = tanhf(z3s[tid * NO + 32 + i]);
            float x = inp[(b0 + tid) * NI + i] * expf(a) + m;
            xs[tid * NI + i] = x;
            Js[tid] -= a;
        }
        __syncthreads();
        if (i == NI - 1) break;

        const int w   = 31 - i;
        const int cnt = (i == 0) ? 34 : 33;
        const int nv  = 33 * w + ((i == 0) ? 1 : 0);

        // ---- Phase B: rank-1 z1 update (units with deg >= i) + extract
        //      newly-final h1 group (deg == i) ----
        float xv[MB];
        #pragma unroll
        for (int mb = 0; mb < MB; ++mb) xv[mb] = xs[mb * NI + i];
        for (int j = tid; j < nv; j += THREADS) {
            int q = j / w;
            int r = i + (j - q * w);
            int h = 31 * q + r;
            float w1 = g_W1T[i * NH + h];
            float zz[MB];
            #pragma unroll
            for (int mb = 0; mb < MB; ++mb) {
                float z = z1s[mb * NH + h] + w1 * xv[mb];
                z1s[mb * NH + h] = z;
                zz[mb] = z;
            }
            if (r == i) {               // group member, k == q
                #pragma unroll
                for (int mb = 0; mb < MB; ++mb)
                    h1g[q * MB + mb] = fmaxf(zz[mb], 0.f);
            }
        }
        __syncthreads();

        // ---- Phase C: rank-cnt z2 update + extract h2 group ----
        for (int j = tid; j < nv; j += THREADS) {
            int q = j / w;
            int r = i + (j - q * w);
            int g = 31 * q + r;
            float acc[MB];
            #pragma unroll
            for (int mb = 0; mb < MB; ++mb) acc[mb] = 0.f;
            #pragma unroll 4
            for (int k = 0; k < cnt; ++k) {
                int h = i + 31 * k;
                float wv = g_W2T[h * NH + g];
                float4 hv0 = *(const float4*)&h1g[k * MB];
                float4 hv1 = *(const float4*)&h1g[k * MB + 4];
                acc[0] += wv * hv0.x; acc[1] += wv * hv0.y;
                acc[2] += wv * hv0.z; acc[3] += wv * hv0.w;
                acc[4] += wv * hv1.x; acc[5] += wv * hv1.y;
                acc[6] += wv * hv1.z; acc[7] += wv * hv1.w;
            }
            float zz[MB];
            #pragma unroll
            for (int mb = 0; mb < MB; ++mb) {
                float z = z2s[mb * NH + g] + acc[mb];
                z2s[mb * NH + g] = z;
                zz[mb] = z;
            }
            if (r == i) {
                #pragma unroll
                for (int mb = 0; mb < MB; ++mb)
                    h2g[q * MB + mb] = fmaxf(zz[mb], 0.f);
            }
        }
        __syncthreads();

        // ---- Phase D: z3 update (outputs with out_deg >= i) ----
        for (int idx = tid; idx < MB * NO; idx += THREADS) {
            int mb = idx >> 6;
            int o  = idx & (NO - 1);
            if ((o & 31) > i) {
                float acc = 0.f;
                #pragma unroll 4
                for (int k = 0; k < cnt; ++k) {
                    int g = i + 31 * k;
                    acc += g_W3T[g * NO + o] * h2g[k * MB + mb];
                }
                z3s[idx] += acc;
            }
        }
        __syncthreads();
    }

    // ---- outputs: x (B x NI) then J (B) ----
    for (int idx = tid; idx < MB * NI; idx += THREADS) {
        int mb = idx >> 5;
        int ii = idx & (NI - 1);
        out[(b0 + mb) * NI + ii] = xs[mb * NI + ii];
    }
    if (tid < MB) out[B * NI + b0 + tid] = Js[tid];
}

// ---------------- launcher ----------------

extern "C" void kernel_launch(void* const* d_in, const int* in_sizes, int n_in,
                              void* d_out, int out_size) {
    const float* inputs = (const float*)d_in[0];
    const float* W1     = (const float*)d_in[1];
    const float* b1     = (const float*)d_in[2];
    const float* W2     = (const float*)d_in[3];
    const float* b2     = (const float*)d_in[4];
    const float* W3     = (const float*)d_in[5];
    const float* b3     = (const float*)d_in[6];

    int B = in_sizes[0] / NI;

    static bool attr_set = false;
    size_t smem_bytes = (size_t)(MB * NH * 2 + MB * NO + MB * NI + 34 * MB * 2 + MB)
                        * sizeof(float);
    if (!attr_set) {
        cudaFuncSetAttribute(made_kernel,
                             cudaFuncAttributeMaxDynamicSharedMemorySize,
                             (int)smem_bytes);
        attr_set = true;
    }

    prep_small<<<(NH * NO + 255) / 256, 256>>>(W1, W3);
    dim3 g2(NH / 32, NH / 32), t2(32, 8);
    prep_w2<<<g2, t2>>>(W2);
    made_kernel<<<B / MB, THREADS, smem_bytes>>>(inputs, b1, b2, b3,
                                                 (float*)d_out, B);
}

// round 3
// speedup vs baseline: 1.6341x; 1.6341x over previous
#include <cuda_runtime.h>
#include <cuda_bf16.h>
#include <math.h>

#define NI 32
#define NH 1024
#define NO 64
#define MB 8
#define THREADS 1024

// Scratch (no device allocation allowed): transposed weights.
__device__ float g_W1T[NI * NH];     // [i][h]
__device__ float g_W2T[NH * NH];     // [h][g]  (W2T[h*NH+g] = W2[g*NH+h])
__device__ float g_W3T[NH * NO];     // [g][o]

// ---------------- prep kernels ----------------

__global__ void prep_small(const float* __restrict__ W1,
                           const float* __restrict__ W3) {
    int t = blockIdx.x * blockDim.x + threadIdx.x;
    if (t < NI * NH) {
        int i = t >> 10;       // /NH
        int h = t & (NH - 1);
        g_W1T[t] = W1[h * NI + i];
    }
    if (t < NH * NO) {
        int g = t >> 6;        // /NO
        int o = t & (NO - 1);
        g_W3T[t] = W3[o * NH + g];
    }
}

__global__ void prep_w2(const float* __restrict__ W2) {
    __shared__ float tile[32][33];
    int bx = blockIdx.x, by = blockIdx.y;
    int tx = threadIdx.x, ty = threadIdx.y;   // 32 x 8
    #pragma unroll
    for (int yy = 0; yy < 32; yy += 8)
        tile[ty + yy][tx] = W2[(by * 32 + ty + yy) * NH + bx * 32 + tx];
    __syncthreads();
    #pragma unroll
    for (int yy = 0; yy < 32; yy += 8)
        g_W2T[(bx * 32 + ty + yy) * NH + by * 32 + tx] = tile[tx][ty + yy];
}

// ---------------- main kernel ----------------
//
// Per CTA: MB batch rows. Running pre-activations z1[MB][NH], z2[MB][NH],
// z3[MB][64] in smem. 32 sequential steps; at step i only ~33-34 hidden
// units (degree == i, deg(h) = h % 31) become final and are pushed forward
// as rank-33 updates. Valid targets at step i: (h % 31) >= i, enumerated
// compactly via j -> (q = j/w, r = i + j%w, h = 31q + r), w = 31 - i.
// Max nv = 33*31 + 1 = 1024 == THREADS, so every phase is single-pass.

__global__ void __launch_bounds__(THREADS)
made_kernel(const float* __restrict__ inp,
            const float* __restrict__ b1,
            const float* __restrict__ b2,
            const float* __restrict__ b3,
            float* __restrict__ out, int B) {
    extern __shared__ float smem[];
    float* z1s = smem;                    // MB*NH
    float* z2s = z1s + MB * NH;           // MB*NH
    float* z3s = z2s + MB * NH;           // MB*NO
    float* xs  = z3s + MB * NO;           // MB*NI
    float* h1g = xs  + MB * NI;           // 34*MB  (layout [k][mb], 16B aligned)
    float* h2g = h1g + 34 * MB;           // 34*MB
    float* Js  = h2g + 34 * MB;           // MB

    const int tid = threadIdx.x;
    const int b0  = blockIdx.x * MB;

    // init state with biases
    for (int idx = tid; idx < MB * NH; idx += THREADS) {
        int h = idx & (NH - 1);
        z1s[idx] = b1[h];
        z2s[idx] = b2[h];
    }
    if (tid < MB * NO) z3s[tid] = b3[tid & (NO - 1)];
    if (tid < MB) Js[tid] = 0.f;
    __syncthreads();

    for (int i = 0; i < NI; ++i) {
        // ---- Phase A: read p[:,i], p[:,32+i]; produce x_i ----
        if (tid < MB) {
            float m = z3s[tid * NO + i];
            float a = tanhf(z3s[tid * NO + 32 + i]);
            float x = inp[(b0 + tid) * NI + i] * expf(a) + m;
            xs[tid * NI + i] = x;
            Js[tid] -= a;
        }
        __syncthreads();
        if (i == NI - 1) break;

        const int w   = 31 - i;
        const int cnt = (i == 0) ? 34 : 33;
        const int nv  = 33 * w + ((i == 0) ? 1 : 0);

        // shared index math for phases B and C
        int q = 0, r = 0, hg = 0;
        const bool act = (tid < nv);
        if (act) {
            q  = tid / w;
            r  = i + (tid - q * w);
            hg = 31 * q + r;
        }
        const bool grp = act && (r == i);

        // ---- Phase B: rank-1 z1 update + extract newly-final h1 group ----
        if (act) {
            float xv[MB];
            #pragma unroll
            for (int mb = 0; mb < MB; ++mb) xv[mb] = xs[mb * NI + i];
            const float w1 = g_W1T[i * NH + hg];
            float zz[MB];
            #pragma unroll
            for (int mb = 0; mb < MB; ++mb) {
                float z = z1s[mb * NH + hg] + w1 * xv[mb];
                z1s[mb * NH + hg] = z;
                zz[mb] = z;
            }
            if (grp) {
                #pragma unroll
                for (int mb = 0; mb < MB; ++mb)
                    h1g[q * MB + mb] = fmaxf(zz[mb], 0.f);
            }
        }
        __syncthreads();

        // ---- Phase C: rank-cnt z2 update + extract h2 group ----
        if (act) {
            float acc[MB];
            #pragma unroll
            for (int mb = 0; mb < MB; ++mb) acc[mb] = 0.f;
            #pragma unroll 8
            for (int k = 0; k < cnt; ++k) {
                int h = i + 31 * k;
                float wv = __ldg(&g_W2T[h * NH + hg]);
                float4 hv0 = *(const float4*)&h1g[k * MB];
                float4 hv1 = *(const float4*)&h1g[k * MB + 4];
                acc[0] += wv * hv0.x; acc[1] += wv * hv0.y;
                acc[2] += wv * hv0.z; acc[3] += wv * hv0.w;
                acc[4] += wv * hv1.x; acc[5] += wv * hv1.y;
                acc[6] += wv * hv1.z; acc[7] += wv * hv1.w;
            }
            float zz[MB];
            #pragma unroll
            for (int mb = 0; mb < MB; ++mb) {
                float z = z2s[mb * NH + hg] + acc[mb];
                z2s[mb * NH + hg] = z;
                zz[mb] = z;
            }
            if (grp) {
                #pragma unroll
                for (int mb = 0; mb < MB; ++mb)
                    h2g[q * MB + mb] = fmaxf(zz[mb], 0.f);
            }
        }
        __syncthreads();

        // ---- Phase D: z3 update (outputs with out_deg >= i), pair-split k ----
        {
            const int pid  = tid >> 1;           // (mb,o) item, 512 of them
            const int half = tid & 1;
            const int mb   = pid >> 6;
            const int o    = pid & (NO - 1);
            const bool on  = ((o & 31) > i);
            float acc = 0.f;
            if (on) {
                #pragma unroll 8
                for (int k = half; k < cnt; k += 2) {
                    int g = i + 31 * k;
                    acc += __ldg(&g_W3T[g * NO + o]) * h2g[k * MB + mb];
                }
            }
            acc += __shfl_down_sync(0xffffffffu, acc, 1);
            if (on && half == 0) z3s[pid] += acc;
        }
        __syncthreads();
    }

    // ---- outputs: x (B x NI) then J (B) ----
    if (tid < MB * NI) {
        int mb = tid >> 5;
        int ii = tid & (NI - 1);
        out[(b0 + mb) * NI + ii] = xs[mb * NI + ii];
    }
    if (tid < MB) out[B * NI + b0 + tid] = Js[tid];
}

// ---------------- launcher ----------------

extern "C" void kernel_launch(void* const* d_in, const int* in_sizes, int n_in,
                              void* d_out, int out_size) {
    const float* inputs = (const float*)d_in[0];
    const float* W1     = (const float*)d_in[1];
    const float* b1     = (const float*)d_in[2];
    const float* W2     = (const float*)d_in[3];
    const float* b2     = (const float*)d_in[4];
    const float* W3     = (const float*)d_in[5];
    const float* b3     = (const float*)d_in[6];

    int B = in_sizes[0] / NI;

    static bool attr_set = false;
    size_t smem_bytes = (size_t)(MB * NH * 2 + MB * NO + MB * NI + 34 * MB * 2 + MB)
                        * sizeof(float);
    if (!attr_set) {
        cudaFuncSetAttribute(made_kernel,
                             cudaFuncAttributeMaxDynamicSharedMemorySize,
                             (int)smem_bytes);
        attr_set = true;
    }

    prep_small<<<(NH * NO + 255) / 256, 256>>>(W1, W3);
    dim3 g2(NH / 32, NH / 32), t2(32, 8);
    prep_w2<<<g2, t2>>>(W2);
    made_kernel<<<B / MB, THREADS, smem_bytes>>>(inputs, b1, b2, b3,
                                                 (float*)d_out, B);
}